// round 14
// baseline (speedup 1.0000x reference)
#include <cuda_runtime.h>

#define BB 32
#define SS 128
#define KN 12
#define KC 10
#define KT 22
#define DD 200
#define D4 50
#define CC 45
#define CP 48
#define CP4 12
#define FF 1000
#define NTOK 4096

#define GT 32
#define NTILES (NTOK / GT)                 // 128
#define NF 1366                            // feat blocks (3 tokens each)
#define NG (NTILES * 5)                    // 640 gemm blocks
#define NBLK (NF + NG)                     // 2006
#define APAD 51                            // shA pitch in float4
#define BROWS 40                           // B rows per stage (5 stages)

__device__ float    g_feat[NTOK * DD];
__device__ float    g_part[5 * NTOK * CP];
__device__ unsigned g_tokflag[NTOK];       // epoch when token ready (0-init)
__device__ int      g_cnt[NTILES];         // per-tile arrivals (self-reset)
__device__ unsigned g_tiles_done = 0;
__device__ unsigned g_epoch = 0;

__device__ __forceinline__ unsigned ld_acq(const unsigned* p) {
    unsigned v;
    asm volatile("ld.acquire.gpu.b32 %0, [%1];" : "=r"(v) : "l"(p) : "memory");
    return v;
}
__device__ __forceinline__ void st_rel(unsigned* p, unsigned v) {
    asm volatile("st.release.gpu.b32 [%0], %1;" :: "l"(p), "r"(v) : "memory");
}

// position of gemm tile t = 5t + F(t), F(t) = #feat blocks covering tokens <= 32t+33
__device__ __forceinline__ int Fof(int t) { return (32 * t + 33) / 3 + 1; }

// ---------------------------------------------------------------------------
// Fused kernel: 2006 blocks of 192 threads. Feat and gemm interleaved in
// dependence order (all producers of a gemm tile precede it -> deadlock-free).
// ---------------------------------------------------------------------------
__global__ void __launch_bounds__(192, 6)
fused_kernel(const int* __restrict__ ngram_ids,
             const int* __restrict__ ngram_mask,
             const int* __restrict__ ctx_ids,
             const int* __restrict__ ctx_mask,
             const float* __restrict__ embed,
             const float* __restrict__ W,
             const float* __restrict__ bias,
             float* __restrict__ out) {
    __shared__ float4 shA[GT * APAD];        // 26112 B (gemm)
    __shared__ float4 shB[BROWS * CP4];      // 7680 B  (gemm)
    __shared__ int s_act[3][24];             // feat
    __shared__ int s_n[3];
    __shared__ int s_last;

    const unsigned E = *(volatile unsigned*)&g_epoch + 1;
    const int bid = blockIdx.x;
    const int tid = threadIdx.x;

    // ---- decode merged order (Bresenham by dependence keys) ----
    int t = bid / 16; if (t > NTILES - 1) t = NTILES - 1;
    while (t >= 0 && 5 * t + Fof(t) > bid) t--;
    while (t < NTILES - 1 && 5 * (t + 1) + Fof(t + 1) <= bid) t++;
    bool isGemm = false; int w = 0;
    if (t >= 0) {
        int base = 5 * t + Fof(t);
        if (bid >= base && bid < base + 5) { isGemm = true; w = bid - base; }
    }

    if (!isGemm) {
        // =================== FEAT: 3 tokens, 64 thr each ===================
        const int f = bid - 5 * (t + 1);
        const int g    = tid >> 6;
        const int lane = tid & 63;
        const int tok  = 3 * f + g;
        const bool valid = (tok < NTOK);

        if (valid && lane < 32) {
            int m = 0, id = 0;
            if (lane < KN) {
                id = ngram_ids[tok * KN + lane];
                m  = ngram_mask[tok * KN + lane];
            } else if (lane < KT) {
                id = ctx_ids[tok * KC + lane - KN];
                m  = ctx_mask[tok * KC + lane - KN];
            }
            unsigned bal = __ballot_sync(0xffffffffu, m != 0);
            if (m) s_act[g][__popc(bal & ((1u << lane) - 1u))] = id;
            if (lane == 0) s_n[g] = __popc(bal);
        }
        __syncthreads();

        if (valid && lane < D4) {
            const int n = s_n[g];
            const int* act = s_act[g];
            const float4* e4 = (const float4*)embed;
            float ax = 0.f, ay = 0.f, az = 0.f, aw = 0.f;
            int j = 0;
            for (; j + 4 <= n; j += 4) {
                float4 a = e4[(long long)act[j + 0] * D4 + lane];
                float4 b = e4[(long long)act[j + 1] * D4 + lane];
                float4 c = e4[(long long)act[j + 2] * D4 + lane];
                float4 d = e4[(long long)act[j + 3] * D4 + lane];
                ax += (a.x + b.x) + (c.x + d.x);
                ay += (a.y + b.y) + (c.y + d.y);
                az += (a.z + b.z) + (c.z + d.z);
                aw += (a.w + b.w) + (c.w + d.w);
            }
            for (; j < n; j++) {
                float4 a = e4[(long long)act[j] * D4 + lane];
                ax += a.x; ay += a.y; az += a.z; aw += a.w;
            }
            float inv = 1.0f / (float)(n > 0 ? n : 1);
            float4 r; r.x = ax * inv; r.y = ay * inv; r.z = az * inv; r.w = aw * inv;
            ((float4*)g_feat)[tok * D4 + lane] = r;
        }

        __syncthreads();
        __threadfence();
        if (tid < 3 && 3 * f + tid < NTOK)
            st_rel(&g_tokflag[3 * f + tid], E);
        return;
    }

    // ======================= GEMM: tile t, window w ========================
    const int tokBase = t * GT;
    const int b  = tokBase / SS;
    const int s0 = tokBase % SS;

    // wait for the 32 tokens this block reads (producers dispatched earlier)
    if (tid < GT) {
        int s = s0 + w - 2 + tid;
        if (s >= 0 && s < SS) {
            const unsigned* fl = &g_tokflag[b * SS + s];
            while (ld_acq(fl) != E) __nanosleep(128);
        }
    }
    __syncthreads();

    const int tg = tid & 15;                 // tokens tg, tg+16
    const int cg = tid >> 4;                 // 0..11

    // stage A rows s0+w-2 .. s0+w+29 (zero halo)
    const float4* gf4 = (const float4*)g_feat;
    for (int i = tid; i < GT * D4; i += 192) {
        int r  = i / D4;
        int dv = i - r * D4;
        int s  = s0 + w - 2 + r;
        float4 v = make_float4(0.f, 0.f, 0.f, 0.f);
        if (s >= 0 && s < SS) v = gf4[(b * SS + s) * D4 + dv];
        shA[r * APAD + dv] = v;
    }

    float p00 = 0.f, p01 = 0.f, p02 = 0.f, p03 = 0.f;
    float p10 = 0.f, p11 = 0.f, p12 = 0.f, p13 = 0.f;
    const float4* W4 = (const float4*)W;     // [45][250] float4
    float* shBf = (float*)shB;

    #pragma unroll
    for (int st = 0; st < 5; st++) {
        __syncthreads();
        // stage B rows [w*200+st*40, +40) directly from W (transpose on store)
        for (int i = tid; i < CP * (BROWS / 4); i += 192) {
            int c  = i / (BROWS / 4);        // 0..47
            int k4 = i - c * (BROWS / 4);    // 0..9
            float4 v = make_float4(0.f, 0.f, 0.f, 0.f);
            if (c < CC) v = W4[c * 250 + w * 50 + st * 10 + k4];
            int kb = k4 * 4;
            shBf[(kb + 0) * CP + c] = v.x;
            shBf[(kb + 1) * CP + c] = v.y;
            shBf[(kb + 2) * CP + c] = v.z;
            shBf[(kb + 3) * CP + c] = v.w;
        }
        __syncthreads();

        const float4* aRow0 = &shA[tg * APAD + st * 10];
        const float4* aRow1 = &shA[(tg + 16) * APAD + st * 10];
        #pragma unroll
        for (int dq = 0; dq < 10; dq++) {
            float4 a0 = aRow0[dq];
            float4 a1 = aRow1[dq];
            float4 b0 = shB[(dq * 4 + 0) * CP4 + cg];
            float4 b1 = shB[(dq * 4 + 1) * CP4 + cg];
            float4 b2 = shB[(dq * 4 + 2) * CP4 + cg];
            float4 b3 = shB[(dq * 4 + 3) * CP4 + cg];
            p00 = fmaf(a0.x, b0.x, p00); p01 = fmaf(a0.x, b0.y, p01);
            p02 = fmaf(a0.x, b0.z, p02); p03 = fmaf(a0.x, b0.w, p03);
            p10 = fmaf(a1.x, b0.x, p10); p11 = fmaf(a1.x, b0.y, p11);
            p12 = fmaf(a1.x, b0.z, p12); p13 = fmaf(a1.x, b0.w, p13);
            p00 = fmaf(a0.y, b1.x, p00); p01 = fmaf(a0.y, b1.y, p01);
            p02 = fmaf(a0.y, b1.z, p02); p03 = fmaf(a0.y, b1.w, p03);
            p10 = fmaf(a1.y, b1.x, p10); p11 = fmaf(a1.y, b1.y, p11);
            p12 = fmaf(a1.y, b1.z, p12); p13 = fmaf(a1.y, b1.w, p13);
            p00 = fmaf(a0.z, b2.x, p00); p01 = fmaf(a0.z, b2.y, p01);
            p02 = fmaf(a0.z, b2.z, p02); p03 = fmaf(a0.z, b2.w, p03);
            p10 = fmaf(a1.z, b2.x, p10); p11 = fmaf(a1.z, b2.y, p11);
            p12 = fmaf(a1.z, b2.z, p12); p13 = fmaf(a1.z, b2.w, p13);
            p00 = fmaf(a0.w, b3.x, p00); p01 = fmaf(a0.w, b3.y, p01);
            p02 = fmaf(a0.w, b3.z, p02); p03 = fmaf(a0.w, b3.w, p03);
            p10 = fmaf(a1.w, b3.x, p10); p11 = fmaf(a1.w, b3.y, p11);
            p12 = fmaf(a1.w, b3.z, p12); p13 = fmaf(a1.w, b3.w, p13);
        }
    }

    float4* part4 = (float4*)g_part;
    {
        float4 v0; v0.x = p00; v0.y = p01; v0.z = p02; v0.w = p03;
        float4 v1; v1.x = p10; v1.y = p11; v1.z = p12; v1.w = p13;
        part4[((long long)w * NTOK + tokBase + tg) * CP4 + cg] = v0;
        part4[((long long)w * NTOK + tokBase + tg + 16) * CP4 + cg] = v1;
    }

    // last-of-5 reduction (fixed w-order -> deterministic)
    __threadfence();
    __syncthreads();
    if (tid == 0) {
        int old = atomicAdd(&g_cnt[t], 1);
        s_last = (old == 4);
    }
    __syncthreads();
    if (!s_last) return;
    __threadfence();

    #pragma unroll
    for (int half = 0; half < 2; half++) {
        int tok = tokBase + tg + half * 16;
        float4 s = make_float4(0.f, 0.f, 0.f, 0.f);
        #pragma unroll
        for (int w2 = 0; w2 < 5; w2++) {
            float4 p = part4[((long long)w2 * NTOK + tok) * CP4 + cg];
            s.x += p.x; s.y += p.y; s.z += p.z; s.w += p.w;
        }
        int c0 = cg * 4;
        float* o = out + (long long)tok * CC;
        o[c0] = s.x + bias[c0];
        if (c0 + 1 < CC) o[c0 + 1] = s.y + bias[c0 + 1];
        if (c0 + 2 < CC) o[c0 + 2] = s.z + bias[c0 + 2];
        if (c0 + 3 < CC) o[c0 + 3] = s.w + bias[c0 + 3];
    }
    if (tid == 0) {
        g_cnt[t] = 0;                        // reset tile counter for next replay
        __threadfence();
        unsigned d = atomicAdd(&g_tiles_done, 1);
        if (d == NTILES - 1) {               // last tile of this launch
            g_tiles_done = 0;
            *(volatile unsigned*)&g_epoch = E;   // advance epoch for next replay
        }
    }
}

// ---------------------------------------------------------------------------
extern "C" void kernel_launch(void* const* d_in, const int* in_sizes, int n_in,
                              void* d_out, int out_size) {
    const int*   ngram_ids  = (const int*)d_in[0];
    const int*   ngram_mask = (const int*)d_in[1];
    const int*   ctx_ids    = (const int*)d_in[2];
    const int*   ctx_mask   = (const int*)d_in[3];
    const float* embed      = (const float*)d_in[4];
    const float* W          = (const float*)d_in[5];
    const float* bias       = (const float*)d_in[6];
    float* out = (float*)d_out;

    fused_kernel<<<NBLK, 192>>>(ngram_ids, ngram_mask, ctx_ids, ctx_mask,
                                embed, W, bias, out);
}

// round 15
// speedup vs baseline: 1.4202x; 1.4202x over previous
#include <cuda_runtime.h>

#define BB 32
#define SS 128
#define KN 12
#define KC 10
#define KT 22
#define DD 200
#define D4 50
#define CC 45
#define CP 48
#define CP4 12
#define FF 1000
#define NTOK 4096

#define FEATB (NTOK / 2)                   // 2048 (2 tokens/block)
#define TR_ELEMS (FF * CP)                 // 48000
#define TR_BLOCKS ((TR_ELEMS + 127) / 128) // 375

#define GT 64                              // tokens per gemm tile
#define NTILES (NTOK / GT)                 // 64
#define NPART 10                           // 5 w x 2 h
#define GEMMB (NTILES * NPART)             // 640
#define AP4 27                             // shA pitch in float4 (108 floats)

__device__ float g_feat[NTOK * DD];        // [tok, D]
__device__ float g_Wt[FF * CP];            // [k, 48] transposed+padded
__device__ float g_part[NPART * NTOK * CP];// [p, tok, 48]
__device__ int   g_cnt[NTILES];            // zero-init; reset by reducer

// ---------------------------------------------------------------------------
// Kernel 1 (R4-proven, unchanged): masked gather+mean, 2 tokens/block,
// ballot-compacted ids, reg-capped; W transpose appended to the grid.
// ---------------------------------------------------------------------------
__global__ void __launch_bounds__(128, 16)
feat_tr_kernel(const int* __restrict__ ngram_ids,
               const int* __restrict__ ngram_mask,
               const int* __restrict__ ctx_ids,
               const int* __restrict__ ctx_mask,
               const float* __restrict__ embed,
               const float* __restrict__ W) {
    if (blockIdx.x >= FEATB) {
        int idx = (blockIdx.x - FEATB) * 128 + threadIdx.x;
        if (idx < TR_ELEMS) {
            int c = idx / FF;
            int k = idx - c * FF;
            g_Wt[k * CP + c] = (c < CC) ? W[c * FF + k] : 0.0f;
        }
        return;
    }

    const int half = threadIdx.x >> 6;
    const int lane = threadIdx.x & 63;
    const int tok  = blockIdx.x * 2 + half;

    __shared__ int s_act[2][24];
    __shared__ int s_cnt[2];

    if (lane < 32) {
        int m = 0, id = 0;
        if (lane < KN) {
            id = ngram_ids[tok * KN + lane];
            m  = ngram_mask[tok * KN + lane];
        } else if (lane < KT) {
            id = ctx_ids[tok * KC + lane - KN];
            m  = ctx_mask[tok * KC + lane - KN];
        }
        unsigned bal = __ballot_sync(0xffffffffu, m != 0);
        if (m) s_act[half][__popc(bal & ((1u << lane) - 1u))] = id;
        if (lane == 0) s_cnt[half] = __popc(bal);
    }
    __syncthreads();

    if (lane >= D4) return;

    const int n = s_cnt[half];
    const int* act = s_act[half];
    const float4* e4 = (const float4*)embed;

    float ax = 0.f, ay = 0.f, az = 0.f, aw = 0.f;
    int j = 0;
    for (; j + 4 <= n; j += 4) {
        float4 a = e4[(long long)act[j + 0] * D4 + lane];
        float4 b = e4[(long long)act[j + 1] * D4 + lane];
        float4 c = e4[(long long)act[j + 2] * D4 + lane];
        float4 d = e4[(long long)act[j + 3] * D4 + lane];
        ax += (a.x + b.x) + (c.x + d.x);
        ay += (a.y + b.y) + (c.y + d.y);
        az += (a.z + b.z) + (c.z + d.z);
        aw += (a.w + b.w) + (c.w + d.w);
    }
    for (; j < n; j++) {
        float4 a = e4[(long long)act[j] * D4 + lane];
        ax += a.x; ay += a.y; az += a.z; aw += a.w;
    }

    float inv = 1.0f / (float)(n > 0 ? n : 1);
    float4 r; r.x = ax * inv; r.y = ay * inv; r.z = az * inv; r.w = aw * inv;
    ((float4*)g_feat)[tok * D4 + lane] = r;
}

// ---------------------------------------------------------------------------
// Kernel 2: per-(w,h) partial GEMM. Grid 640 = 64 tiles x 5 w x 2 h,
// 192 threads, 46.8 KB static smem (4 CTAs/SM). Thread = 4 tok x 4 c
// (16 acc): per dq-step 8 LDS.128 per 64 FFMA -> FMA-bound inner loop.
// shA pitch 27 float4 = bank-conflict-free A fragment loads.
// Fused last-of-10 reduction (fixed order -> deterministic).
// ---------------------------------------------------------------------------
__global__ void __launch_bounds__(192, 4)
gemm_kernel(const float* __restrict__ bias,
            float* __restrict__ out) {
    __shared__ float4 shA[GT * AP4];         // 27648 B
    __shared__ float4 shB[100 * CP4];        // 19200 B
    __shared__ int s_last;

    const int q = blockIdx.x;
    const int tile = q / NPART;
    const int p = q - tile * NPART;          // 0..9 = w*2 + h
    const int w = p >> 1;
    const int h = p & 1;
    const int tokBase = tile * GT;
    const int b  = tokBase / SS;
    const int s0 = tokBase % SS;

    const int tid = threadIdx.x;
    const int tg = tid & 15;                 // tokens tg, +16, +32, +48
    const int cg = tid >> 4;                 // 0..11

    // stage A: 64 w-shifted rows (zero halo), k cols [h*100, h*100+100)
    const float4* gf4 = (const float4*)g_feat;
    for (int i = tid; i < GT * 25; i += 192) {
        int r  = i / 25;
        int dv = i - r * 25;
        int s  = s0 + w - 2 + r;
        float4 v = make_float4(0.f, 0.f, 0.f, 0.f);
        if (s >= 0 && s < SS) v = gf4[(b * SS + s) * D4 + h * 25 + dv];
        shA[r * AP4 + dv] = v;
    }
    // stage B: 100 k-rows of g_Wt for this (w,h)
    const float4* Wt4 = (const float4*)g_Wt;
    for (int i = tid; i < 100 * CP4; i += 192)
        shB[i] = Wt4[(w * DD + h * 100) * CP4 + i];
    __syncthreads();

    float p00 = 0.f, p01 = 0.f, p02 = 0.f, p03 = 0.f;
    float p10 = 0.f, p11 = 0.f, p12 = 0.f, p13 = 0.f;
    float p20 = 0.f, p21 = 0.f, p22 = 0.f, p23 = 0.f;
    float p30 = 0.f, p31 = 0.f, p32 = 0.f, p33 = 0.f;

    const float4* aR0 = &shA[(tg +  0) * AP4];
    const float4* aR1 = &shA[(tg + 16) * AP4];
    const float4* aR2 = &shA[(tg + 32) * AP4];
    const float4* aR3 = &shA[(tg + 48) * AP4];

    #pragma unroll
    for (int dq = 0; dq < 25; dq++) {
        float4 a0 = aR0[dq];
        float4 a1 = aR1[dq];
        float4 a2 = aR2[dq];
        float4 a3 = aR3[dq];
        float4 b0 = shB[(dq * 4 + 0) * CP4 + cg];
        float4 b1 = shB[(dq * 4 + 1) * CP4 + cg];
        float4 b2 = shB[(dq * 4 + 2) * CP4 + cg];
        float4 b3 = shB[(dq * 4 + 3) * CP4 + cg];

        p00 = fmaf(a0.x, b0.x, p00); p01 = fmaf(a0.x, b0.y, p01);
        p02 = fmaf(a0.x, b0.z, p02); p03 = fmaf(a0.x, b0.w, p03);
        p10 = fmaf(a1.x, b0.x, p10); p11 = fmaf(a1.x, b0.y, p11);
        p12 = fmaf(a1.x, b0.z, p12); p13 = fmaf(a1.x, b0.w, p13);
        p20 = fmaf(a2.x, b0.x, p20); p21 = fmaf(a2.x, b0.y, p21);
        p22 = fmaf(a2.x, b0.z, p22); p23 = fmaf(a2.x, b0.w, p23);
        p30 = fmaf(a3.x, b0.x, p30); p31 = fmaf(a3.x, b0.y, p31);
        p32 = fmaf(a3.x, b0.z, p32); p33 = fmaf(a3.x, b0.w, p33);

        p00 = fmaf(a0.y, b1.x, p00); p01 = fmaf(a0.y, b1.y, p01);
        p02 = fmaf(a0.y, b1.z, p02); p03 = fmaf(a0.y, b1.w, p03);
        p10 = fmaf(a1.y, b1.x, p10); p11 = fmaf(a1.y, b1.y, p11);
        p12 = fmaf(a1.y, b1.z, p12); p13 = fmaf(a1.y, b1.w, p13);
        p20 = fmaf(a2.y, b1.x, p20); p21 = fmaf(a2.y, b1.y, p21);
        p22 = fmaf(a2.y, b1.z, p22); p23 = fmaf(a2.y, b1.w, p23);
        p30 = fmaf(a3.y, b1.x, p30); p31 = fmaf(a3.y, b1.y, p31);
        p32 = fmaf(a3.y, b1.z, p32); p33 = fmaf(a3.y, b1.w, p33);

        p00 = fmaf(a0.z, b2.x, p00); p01 = fmaf(a0.z, b2.y, p01);
        p02 = fmaf(a0.z, b2.z, p02); p03 = fmaf(a0.z, b2.w, p03);
        p10 = fmaf(a1.z, b2.x, p10); p11 = fmaf(a1.z, b2.y, p11);
        p12 = fmaf(a1.z, b2.z, p12); p13 = fmaf(a1.z, b2.w, p13);
        p20 = fmaf(a2.z, b2.x, p20); p21 = fmaf(a2.z, b2.y, p21);
        p22 = fmaf(a2.z, b2.z, p22); p23 = fmaf(a2.z, b2.w, p23);
        p30 = fmaf(a3.z, b2.x, p30); p31 = fmaf(a3.z, b2.y, p31);
        p32 = fmaf(a3.z, b2.z, p32); p33 = fmaf(a3.z, b2.w, p33);

        p00 = fmaf(a0.w, b3.x, p00); p01 = fmaf(a0.w, b3.y, p01);
        p02 = fmaf(a0.w, b3.z, p02); p03 = fmaf(a0.w, b3.w, p03);
        p10 = fmaf(a1.w, b3.x, p10); p11 = fmaf(a1.w, b3.y, p11);
        p12 = fmaf(a1.w, b3.z, p12); p13 = fmaf(a1.w, b3.w, p13);
        p20 = fmaf(a2.w, b3.x, p20); p21 = fmaf(a2.w, b3.y, p21);
        p22 = fmaf(a2.w, b3.z, p22); p23 = fmaf(a2.w, b3.w, p23);
        p30 = fmaf(a3.w, b3.x, p30); p31 = fmaf(a3.w, b3.y, p31);
        p32 = fmaf(a3.w, b3.z, p32); p33 = fmaf(a3.w, b3.w, p33);
    }

    // write partials (4 tokens per thread)
    float4* part4 = (float4*)g_part;
    {
        float4 v;
        v.x = p00; v.y = p01; v.z = p02; v.w = p03;
        part4[((long long)p * NTOK + tokBase + tg +  0) * CP4 + cg] = v;
        v.x = p10; v.y = p11; v.z = p12; v.w = p13;
        part4[((long long)p * NTOK + tokBase + tg + 16) * CP4 + cg] = v;
        v.x = p20; v.y = p21; v.z = p22; v.w = p23;
        part4[((long long)p * NTOK + tokBase + tg + 32) * CP4 + cg] = v;
        v.x = p30; v.y = p31; v.z = p32; v.w = p33;
        part4[((long long)p * NTOK + tokBase + tg + 48) * CP4 + cg] = v;
    }

    // last-of-10 reduction (fixed p-order -> deterministic)
    __threadfence();
    __syncthreads();
    if (tid == 0) {
        int old = atomicAdd(&g_cnt[tile], 1);
        s_last = (old == NPART - 1);
    }
    __syncthreads();
    if (!s_last) return;
    __threadfence();

    for (int i = tid; i < GT * CP4; i += 192) {
        int tokOff = i / CP4;
        int c4 = i - tokOff * CP4;
        int tok = tokBase + tokOff;
        float4 s = make_float4(0.f, 0.f, 0.f, 0.f);
        #pragma unroll
        for (int pp = 0; pp < NPART; pp++) {
            float4 v = part4[((long long)pp * NTOK + tok) * CP4 + c4];
            s.x += v.x; s.y += v.y; s.z += v.z; s.w += v.w;
        }
        int c0 = c4 * 4;
        float* o = out + (long long)tok * CC;
        if (c0 + 0 < CC) o[c0 + 0] = s.x + bias[c0 + 0];
        if (c0 + 1 < CC) o[c0 + 1] = s.y + bias[c0 + 1];
        if (c0 + 2 < CC) o[c0 + 2] = s.z + bias[c0 + 2];
        if (c0 + 3 < CC) o[c0 + 3] = s.w + bias[c0 + 3];
    }
    __syncthreads();
    if (tid == 0) g_cnt[tile] = 0;           // reset for next graph replay
}

// ---------------------------------------------------------------------------
extern "C" void kernel_launch(void* const* d_in, const int* in_sizes, int n_in,
                              void* d_out, int out_size) {
    const int*   ngram_ids  = (const int*)d_in[0];
    const int*   ngram_mask = (const int*)d_in[1];
    const int*   ctx_ids    = (const int*)d_in[2];
    const int*   ctx_mask   = (const int*)d_in[3];
    const float* embed      = (const float*)d_in[4];
    const float* W          = (const float*)d_in[5];
    const float* bias       = (const float*)d_in[6];
    float* out = (float*)d_out;

    feat_tr_kernel<<<FEATB + TR_BLOCKS, 128>>>(
        ngram_ids, ngram_mask, ctx_ids, ctx_mask, embed, W);
    gemm_kernel<<<GEMMB, 192>>>(bias, out);
}